// round 7
// baseline (speedup 1.0000x reference)
#include <cuda_runtime.h>

#define G 128
#define TPB 256
#define T_STEPS 220
#define ZONES 8
#define ZPITCH 152      // float4 per zone row (128 slots + 24 pad -> 2432B stride)

// Seqlock exchange: 4 phases x 8 zone copies x 128 slots of {v0,v1,seq,seq}.
// Producer k writes slot k in all 8 zones; consumer k polls only zone (k&7).
// Contiguous slots -> sector coalescing; zone stride spreads L2 slice hash.
__device__ float4 g_comm[4][ZONES][ZPITCH];

__device__ __forceinline__ void ldv4(const float4* p, float& a, float& b,
                                     unsigned& s0, unsigned& s1) {
    unsigned x, y;
    asm volatile("ld.volatile.global.v4.b32 {%0,%1,%2,%3}, [%4];"
                 : "=r"(x), "=r"(y), "=r"(s0), "=r"(s1) : "l"(p));
    a = __uint_as_float(x);
    b = __uint_as_float(y);
}
__device__ __forceinline__ void stv4(float4* p, float a, float b, unsigned s) {
    asm volatile("st.volatile.global.v4.b32 [%0], {%1,%2,%3,%4};"
                 :: "l"(p), "r"(__float_as_uint(a)), "r"(__float_as_uint(b)),
                    "r"(s), "r"(s));
}
// Producer-side: replicate slot to all zones (independent STGs, ~40cyc issue).
__device__ __forceinline__ void publish(int phase, int k, float a, float b,
                                        unsigned seq) {
#pragma unroll
    for (int z = 0; z < ZONES; z++) stv4(&g_comm[phase][z][k], a, b, seq);
}
__device__ __forceinline__ float wreduce(float v) {
    v += __shfl_xor_sync(0xffffffffu, v, 16);
    v += __shfl_xor_sync(0xffffffffu, v, 8);
    v += __shfl_xor_sync(0xffffffffu, v, 4);
    v += __shfl_xor_sync(0xffffffffu, v, 2);
    v += __shfl_xor_sync(0xffffffffu, v, 1);
    return v;
}
__device__ __forceinline__ void wreduce2(float& a, float& b) {
#pragma unroll
    for (int m = 16; m >= 1; m >>= 1) {
        a += __shfl_xor_sync(0xffffffffu, a, m);
        b += __shfl_xor_sync(0xffffffffu, b, m);
    }
}
__device__ __forceinline__ void wreduce4(float& a, float& b, float& c, float& d) {
#pragma unroll
    for (int m = 16; m >= 1; m >>= 1) {
        a += __shfl_xor_sync(0xffffffffu, a, m);
        b += __shfl_xor_sync(0xffffffffu, b, m);
        c += __shfl_xor_sync(0xffffffffu, c, m);
        d += __shfl_xor_sync(0xffffffffu, d, m);
    }
}
// Fast activations (~1e-6 rel err; logit gaps >> that, argmax-safe)
__device__ __forceinline__ float fsig(float x) {
    return __fdividef(1.0f, 1.0f + __expf(-x));
}
__device__ __forceinline__ float ftanh(float x) {
    return 1.0f - __fdividef(2.0f, __expf(2.0f * x) + 1.0f);
}
__device__ __forceinline__ float dot256(const float* w, const float* x, int lane) {
    const float4* w4 = (const float4*)w;
    const float4* x4 = (const float4*)x;
    float s = 0.f;
#pragma unroll
    for (int i = 0; i < 2; i++) {
        float4 a = w4[i * 32 + lane], b = x4[i * 32 + lane];
        s += a.x * b.x + a.y * b.y + a.z * b.z + a.w * b.w;
    }
    return s;
}
// Warps 0-3 poll this CTA's zone: predicated reload (satisfied lanes go quiet).
__device__ __forceinline__ void gather(int phase, int zone, float* dst,
                                       unsigned seq, int wid, int lane) {
    if (wid < 4) {
        int s = wid * 32 + lane;
        const float4* p = &g_comm[phase][zone][s];
        float a = 0.f, b = 0.f;
        unsigned s0, s1;
        bool ok = false;
        do {
            if (!ok) {
                ldv4(p, a, b, s0, s1);
                ok = (s0 == seq) && (s1 == seq);
            }
        } while (!__all_sync(0xffffffffu, ok));
        dst[2 * s]     = a;
        dst[2 * s + 1] = b;
    }
    __syncthreads();
}

// SMEM layout (floats)
#define OFF_L0W   0       // 8 x 512  layer0 [Wih(:,0:256) | Whh]
#define OFF_WH1   4096    // 8 x 256
#define OFF_WH2   6144    // 8 x 256
#define OFF_WI1   8192    // 8 x 256
#define OFF_WI2   10240   // 8 x 256
#define OFF_W1R   12288   // 2 x 256
#define OFF_W2S   12800   // 33 x 256
#define OFF_EMB   21248   // 33 x 256
#define OFF_H0S   29696   // 256
#define OFF_H1S   29952
#define OFF_H2S   30208
#define OFF_RS    30464
#define OFF_GT    30720   // 8
#define OFF_PA    30728   // 8
#define OFF_PB    30736
#define OFF_PC    30744
#define OFF_PRED  30752   // 33
#define OFF_BA    30788   // 8
#define OFF_BB    30796
#define OFF_BC    30804
#define OFF_B1R   30812   // 2
#define OFF_B2S   30816   // 33
#define SMEM_FLOATS 30852

__global__ void __launch_bounds__(TPB, 1)
speller_kernel(const float* __restrict__ embed_g,
               const float* __restrict__ Wih0,
               const float* __restrict__ Wihr,
               const float* __restrict__ Whh,
               const float* __restrict__ bih,
               const float* __restrict__ bhh,
               const float* __restrict__ W1,
               const float* __restrict__ b1,
               const float* __restrict__ W2,
               const float* __restrict__ b2,
               const float* __restrict__ h0in,
               const float* __restrict__ c0in,
               float* __restrict__ out)
{
    extern __shared__ float sm[];
    float* l0w  = sm + OFF_L0W;
    float* wh1  = sm + OFF_WH1;
    float* wh2  = sm + OFF_WH2;
    float* wi1  = sm + OFF_WI1;
    float* wi2  = sm + OFF_WI2;
    float* w1r  = sm + OFF_W1R;
    float* w2s  = sm + OFF_W2S;
    float* embs = sm + OFF_EMB;
    float* h0s  = sm + OFF_H0S;
    float* h1s  = sm + OFF_H1S;
    float* h2s  = sm + OFF_H2S;
    float* rs   = sm + OFF_RS;
    float* gT   = sm + OFF_GT;
    float* pA   = sm + OFF_PA;
    float* pB   = sm + OFF_PB;
    float* pC   = sm + OFF_PC;
    float* pred = sm + OFF_PRED;
    float* biasA = sm + OFF_BA;
    float* biasB = sm + OFF_BB;
    float* biasC = sm + OFF_BC;
    float* b1r  = sm + OFF_B1R;
    float* b2s  = sm + OFF_B2S;

    const int tid  = threadIdx.x;
    const int wid  = tid >> 5;
    const int lane = tid & 31;
    const int k    = blockIdx.x;
    const int zone = k & (ZONES - 1);
    const int j0   = 2 * k;          // this CTA's hidden-unit pair

    // ---- One-time weight staging (ctx columns are all-zero: dropped) ----
    for (int idx = tid; idx < 8 * 512; idx += TPB) {
        int r = idx >> 9, c = idx & 511;
        int row = ((r >> 1) << 8) + j0 + (r & 1);        // gate*256 + unit
        l0w[idx] = (c < 256) ? Wih0[row * 384 + c] : Whh[row * 256 + (c - 256)];
    }
    for (int idx = tid; idx < 8 * 256; idx += TPB) {
        int r = idx >> 8, c = idx & 255;
        int row = ((r >> 1) << 8) + j0 + (r & 1);
        wh1[idx] = Whh[(1024 + row) * 256 + c];
        wh2[idx] = Whh[(2048 + row) * 256 + c];
        wi1[idx] = Wihr[row * 256 + c];
        wi2[idx] = Wihr[(1024 + row) * 256 + c];
    }
    for (int idx = tid; idx < 512; idx += TPB) {
        int u = idx >> 8, c = idx & 255;
        w1r[idx] = W1[(j0 + u) * 384 + c];
    }
    for (int idx = tid; idx < 33 * 256; idx += TPB) {
        w2s[idx]  = W2[idx];
        embs[idx] = embed_g[idx];
    }
    for (int idx = tid; idx < 256; idx += TPB) {
        h0s[idx] = h0in[idx];
        h1s[idx] = h0in[256 + idx];
        h2s[idx] = h0in[512 + idx];
    }
    if (tid < 8) {
        int row = ((tid >> 1) << 8) + j0 + (tid & 1);
        biasA[tid] = bih[row] + bhh[row];
        biasB[tid] = bih[1024 + row] + bhh[1024 + row];
        biasC[tid] = bih[2048 + row] + bhh[2048 + row];
    }
    if (tid < 2)  b1r[tid] = b1[j0 + tid];
    if (tid < 33) b2s[tid] = b2[tid];

    float cA = 0.f, cB = 0.f, cC = 0.f;     // cell states in warp0 lanes 0,1
    if (tid < 2) {
        cA = c0in[j0 + tid];
        cB = c0in[256 + j0 + tid];
        cC = c0in[512 + j0 + tid];
    }
    int ch = 0;
    __syncthreads();

    // ---- Initial recurrent partials from h(t=0) ----
    {
        float s0 = dot256(l0w + wid * 512 + 256, h0s, lane);
        float s1 = dot256(wh1 + wid * 256, h1s, lane);
        float s2 = dot256(wh2 + wid * 256, h2s, lane);
        s0 = wreduce(s0); s1 = wreduce(s1); s2 = wreduce(s2);
        if (lane == 0) {
            pA[wid] = s0 + biasA[wid];
            pB[wid] = s1 + biasB[wid];
            pC[wid] = s2 + biasC[wid];
        }
    }
    __syncthreads();

    for (int t = 0; t < T_STEPS; t++) {
        const unsigned seq = (unsigned)(t + 1);

        // ===== Phase A (lite): embed dot + precomputed recurrent partial =====
        {
            float s = wreduce(dot256(l0w + wid * 512, embs + ch * 256, lane));
            if (lane == 0) {
                float g = s + pA[wid];
                gT[wid] = (wid == 4 || wid == 5) ? ftanh(g) : fsig(g);
            }
        }
        __syncthreads();
        if (wid == 0) {
            float h = 0.f;
            if (lane < 2) {
                cA = gT[2 + lane] * cA + gT[lane] * gT[4 + lane];
                h  = gT[6 + lane] * ftanh(cA);
            }
            float hb = __shfl_sync(0xffffffffu, h, 1);
            if (lane == 0) publish(0, k, h, hb, seq);
        }

        // ===== Phase B: wait all h0, layer1 gates =====
        gather(0, zone, h0s, seq, wid, lane);
        {
            float s = wreduce(dot256(wi1 + wid * 256, h0s, lane));
            if (lane == 0) {
                float g = s + pB[wid];
                gT[wid] = (wid == 4 || wid == 5) ? ftanh(g) : fsig(g);
            }
        }
        __syncthreads();
        if (wid == 0) {
            float h = 0.f;
            if (lane < 2) {
                cB = gT[2 + lane] * cB + gT[lane] * gT[4 + lane];
                h  = gT[6 + lane] * ftanh(cB);
            }
            float hb = __shfl_sync(0xffffffffu, h, 1);
            if (lane == 0) publish(1, k, h, hb, seq);
        }

        // ===== Phase C: wait all h1, layer2 gates =====
        gather(1, zone, h1s, seq, wid, lane);
        {
            float s = wreduce(dot256(wi2 + wid * 256, h1s, lane));
            if (lane == 0) {
                float g = s + pC[wid];
                gT[wid] = (wid == 4 || wid == 5) ? ftanh(g) : fsig(g);
            }
        }
        __syncthreads();
        if (wid == 0) {
            float h = 0.f;
            if (lane < 2) {
                cC = gT[2 + lane] * cC + gT[lane] * gT[4 + lane];
                h  = gT[6 + lane] * ftanh(cC);
            }
            float hb = __shfl_sync(0xffffffffu, h, 1);
            if (lane == 0) publish(2, k, h, hb, seq);
        }

        // ===== Phase D: wait all h2; warp0 publishes both r rows =====
        gather(2, zone, h2s, seq, wid, lane);
        if (wid == 0) {
            float s0 = dot256(w1r, h2s, lane);
            float s1 = dot256(w1r + 256, h2s, lane);
            wreduce2(s0, s1);
            if (lane == 0) {
                float r0 = fmaxf(s0 + b1r[0], 0.f);
                float r1 = fmaxf(s1 + b1r[1], 0.f);
                publish(3, k, r0, r1, seq);
            }
        }
        // Overlap (off critical path): next step's recurrent partials
        {
            float s0 = dot256(l0w + wid * 512 + 256, h0s, lane);
            float s1 = dot256(wh1 + wid * 256, h1s, lane);
            float s2 = dot256(wh2 + wid * 256, h2s, lane);
            s0 = wreduce(s0); s1 = wreduce(s1); s2 = wreduce(s2);
            if (lane == 0) {
                pA[wid] = s0 + biasA[wid];
                pB[wid] = s1 + biasB[wid];
                pC[wid] = s2 + biasC[wid];
            }
        }

        // ===== Phase E: wait all r, redundant classifier + argmax + output =====
        gather(3, zone, rs, seq, wid, lane);
        {
            float s0 = dot256(w2s + wid * 256, rs, lane);
            float s1 = dot256(w2s + (wid + 8) * 256, rs, lane);
            float s2 = dot256(w2s + (wid + 16) * 256, rs, lane);
            float s3 = dot256(w2s + (wid + 24) * 256, rs, lane);
            wreduce4(s0, s1, s2, s3);
            if (lane == 0) {
                pred[wid]      = s0 + b2s[wid];
                pred[wid + 8]  = s1 + b2s[wid + 8];
                pred[wid + 16] = s2 + b2s[wid + 16];
                pred[wid + 24] = s3 + b2s[wid + 24];
            }
            if (wid == 0) {
                float s4 = wreduce(dot256(w2s + 32 * 256, rs, lane));
                if (lane == 0) pred[32] = s4 + b2s[32];
            }
        }
        __syncthreads();
        {
            float best = pred[0];
            int bi = 0;
#pragma unroll
            for (int v = 1; v < 33; v++) {
                float p = pred[v];
                if (p > best) { best = p; bi = v; }
            }
            ch = bi;   // bit-identical in every CTA -> uniform feedback
        }
        // write this CTA's 8 identical batch rows: out[b, t, 0:33]
        for (int idx = tid; idx < 8 * 33; idx += TPB) {
            int bl = idx / 33, v = idx - bl * 33;
            out[((size_t)(j0 * 4 + bl) * T_STEPS + t) * 33 + v] = pred[v];
        }
    }
}

extern "C" void kernel_launch(void* const* d_in, const int* in_sizes, int n_in,
                              void* d_out, int out_size) {
    // metadata order: labels, embed, Wih0, Wih_rest, Whh, bih, bhh,
    //                 W1, b1, W2, b2, h0, c0
    const float* embed = (const float*)d_in[1];
    const float* Wih0  = (const float*)d_in[2];
    const float* Wihr  = (const float*)d_in[3];
    const float* Whh   = (const float*)d_in[4];
    const float* bih   = (const float*)d_in[5];
    const float* bhh   = (const float*)d_in[6];
    const float* W1    = (const float*)d_in[7];
    const float* b1    = (const float*)d_in[8];
    const float* W2    = (const float*)d_in[9];
    const float* b2    = (const float*)d_in[10];
    const float* h0    = (const float*)d_in[11];
    const float* c0    = (const float*)d_in[12];
    float* out = (float*)d_out;

    size_t smem = (size_t)SMEM_FLOATS * sizeof(float);
    cudaFuncSetAttribute(speller_kernel,
                         cudaFuncAttributeMaxDynamicSharedMemorySize,
                         (int)smem);
    speller_kernel<<<G, TPB, smem>>>(embed, Wih0, Wihr, Whh, bih, bhh,
                                     W1, b1, W2, b2, h0, c0, out);
}

// round 8
// speedup vs baseline: 1.1626x; 1.1626x over previous
#include <cuda_runtime.h>

#define G 64            // CTAs; each owns 4 hidden units per layer
#define U 4             // units per CTA
#define TPB 256
#define T_STEPS 220
#define CSTRIDE 16      // float4 per CTA slot group (256B stride -> slice spread)

// Seqlock exchange: per phase, 64 CTA slot-groups strided 256B apart.
// CTA k publishes two adjacent float4s (same 32B sector):
//   [k*16+0] = {v0, v1, seq, seq},  [k*16+1] = {v2, v3, seq, seq}
// Data + flag arrive in one 16B volatile load per lane.
__device__ float4 g_comm[4][G * CSTRIDE];

__device__ __forceinline__ void ldv4(const float4* p, float& a, float& b,
                                     unsigned& s0, unsigned& s1) {
    unsigned x, y;
    asm volatile("ld.volatile.global.v4.b32 {%0,%1,%2,%3}, [%4];"
                 : "=r"(x), "=r"(y), "=r"(s0), "=r"(s1) : "l"(p));
    a = __uint_as_float(x);
    b = __uint_as_float(y);
}
__device__ __forceinline__ void stv4(float4* p, float a, float b, unsigned s) {
    asm volatile("st.volatile.global.v4.b32 [%0], {%1,%2,%3,%4};"
                 :: "l"(p), "r"(__float_as_uint(a)), "r"(__float_as_uint(b)),
                    "r"(s), "r"(s));
}
__device__ __forceinline__ float wreduce(float v) {
#pragma unroll
    for (int m = 16; m >= 1; m >>= 1) v += __shfl_xor_sync(0xffffffffu, v, m);
    return v;
}
__device__ __forceinline__ void wreduce2(float& a, float& b) {
#pragma unroll
    for (int m = 16; m >= 1; m >>= 1) {
        a += __shfl_xor_sync(0xffffffffu, a, m);
        b += __shfl_xor_sync(0xffffffffu, b, m);
    }
}
__device__ __forceinline__ void wreduce4(float& a, float& b, float& c, float& d) {
#pragma unroll
    for (int m = 16; m >= 1; m >>= 1) {
        a += __shfl_xor_sync(0xffffffffu, a, m);
        b += __shfl_xor_sync(0xffffffffu, b, m);
        c += __shfl_xor_sync(0xffffffffu, c, m);
        d += __shfl_xor_sync(0xffffffffu, d, m);
    }
}
// Fast activations (~1e-6 rel err; argmax-safe vs observed 3e-7 pipeline err)
__device__ __forceinline__ float fsig(float x) {
    return __fdividef(1.0f, 1.0f + __expf(-x));
}
__device__ __forceinline__ float ftanh(float x) {
    return 1.0f - __fdividef(2.0f, __expf(2.0f * x) + 1.0f);
}
__device__ __forceinline__ float dot256(const float* w, const float* x, int lane) {
    const float4* w4 = (const float4*)w;
    const float4* x4 = (const float4*)x;
    float s = 0.f;
#pragma unroll
    for (int i = 0; i < 2; i++) {
        float4 a = w4[i * 32 + lane], b = x4[i * 32 + lane];
        s += a.x * b.x + a.y * b.y + a.z * b.z + a.w * b.w;
    }
    return s;
}
// Warps 0-3 poll 128 half-slots (64 CTAs x 2 float4), predicated re-poll.
__device__ __forceinline__ void gather(int phase, float* dst, unsigned seq,
                                       int wid, int lane) {
    if (wid < 4) {
        int s = wid * 32 + lane;               // 0..127
        const float4* p = &g_comm[phase][(s >> 1) * CSTRIDE + (s & 1)];
        float a = 0.f, b = 0.f;
        unsigned s0, s1;
        bool ok = false;
        do {
            if (!ok) {
                ldv4(p, a, b, s0, s1);
                ok = (s0 == seq) && (s1 == seq);
            }
        } while (!__all_sync(0xffffffffu, ok));
        dst[2 * s]     = a;
        dst[2 * s + 1] = b;
    }
    __syncthreads();
}

// SMEM layout (floats)
#define OFF_L0W   0                 // 16 x 512  layer0 [Wih(:,0:256) | Whh]
#define OFF_WH1   (OFF_L0W + 8192)  // 16 x 256
#define OFF_WH2   (OFF_WH1 + 4096)
#define OFF_WI1   (OFF_WH2 + 4096)
#define OFF_WI2   (OFF_WI1 + 4096)
#define OFF_W1R   (OFF_WI2 + 4096)  // 4 x 256
#define OFF_W2S   (OFF_W1R + 1024)  // 33 x 256
#define OFF_EMB   (OFF_W2S + 8448)  // 33 x 256
#define OFF_H0S   (OFF_EMB + 8448)  // 256
#define OFF_H1S   (OFF_H0S + 256)
#define OFF_H2S   (OFF_H1S + 256)
#define OFF_RS    (OFF_H2S + 256)
#define OFF_GT    (OFF_RS + 256)    // 16
#define OFF_PA    (OFF_GT + 16)     // 16
#define OFF_PB    (OFF_PA + 16)
#define OFF_PC    (OFF_PB + 16)
#define OFF_PRED  (OFF_PC + 16)     // 33
#define OFF_BA    (OFF_PRED + 36)   // 16
#define OFF_BB    (OFF_BA + 16)
#define OFF_BC    (OFF_BB + 16)
#define OFF_B1R   (OFF_BC + 16)     // 4
#define OFF_B2S   (OFF_B1R + 4)     // 33
#define SMEM_FLOATS (OFF_B2S + 36)

__global__ void __launch_bounds__(TPB, 1)
speller_kernel(const float* __restrict__ embed_g,
               const float* __restrict__ Wih0,
               const float* __restrict__ Wihr,
               const float* __restrict__ Whh,
               const float* __restrict__ bih,
               const float* __restrict__ bhh,
               const float* __restrict__ W1,
               const float* __restrict__ b1,
               const float* __restrict__ W2,
               const float* __restrict__ b2,
               const float* __restrict__ h0in,
               const float* __restrict__ c0in,
               float* __restrict__ out)
{
    extern __shared__ float sm[];
    float* l0w  = sm + OFF_L0W;
    float* wh1  = sm + OFF_WH1;
    float* wh2  = sm + OFF_WH2;
    float* wi1  = sm + OFF_WI1;
    float* wi2  = sm + OFF_WI2;
    float* w1r  = sm + OFF_W1R;
    float* w2s  = sm + OFF_W2S;
    float* embs = sm + OFF_EMB;
    float* h0s  = sm + OFF_H0S;
    float* h1s  = sm + OFF_H1S;
    float* h2s  = sm + OFF_H2S;
    float* rs   = sm + OFF_RS;
    float* gT   = sm + OFF_GT;
    float* pA   = sm + OFF_PA;
    float* pB   = sm + OFF_PB;
    float* pC   = sm + OFF_PC;
    float* pred = sm + OFF_PRED;
    float* biasA = sm + OFF_BA;
    float* biasB = sm + OFF_BB;
    float* biasC = sm + OFF_BC;
    float* b1r  = sm + OFF_B1R;
    float* b2s  = sm + OFF_B2S;

    const int tid  = threadIdx.x;
    const int wid  = tid >> 5;
    const int lane = tid & 31;
    const int k    = blockIdx.x;
    const int j0   = U * k;          // first owned hidden unit

    // ---- One-time weight staging (ctx columns are all-zero: dropped) ----
    // Row order r = gate*4 + u  (gate: 0=i,1=f,2=g,3=o ; u: unit within CTA)
    for (int idx = tid; idx < 16 * 512; idx += TPB) {
        int r = idx >> 9, c = idx & 511;
        int rg = ((r >> 2) << 8) + j0 + (r & 3);
        l0w[idx] = (c < 256) ? Wih0[rg * 384 + c] : Whh[rg * 256 + (c - 256)];
    }
    for (int idx = tid; idx < 16 * 256; idx += TPB) {
        int r = idx >> 8, c = idx & 255;
        int rg = ((r >> 2) << 8) + j0 + (r & 3);
        wh1[idx] = Whh[(1024 + rg) * 256 + c];
        wh2[idx] = Whh[(2048 + rg) * 256 + c];
        wi1[idx] = Wihr[rg * 256 + c];
        wi2[idx] = Wihr[(1024 + rg) * 256 + c];
    }
    for (int idx = tid; idx < U * 256; idx += TPB) {
        int u = idx >> 8, c = idx & 255;
        w1r[idx] = W1[(j0 + u) * 384 + c];
    }
    for (int idx = tid; idx < 33 * 256; idx += TPB) {
        w2s[idx]  = W2[idx];
        embs[idx] = embed_g[idx];
    }
    for (int idx = tid; idx < 256; idx += TPB) {
        h0s[idx] = h0in[idx];
        h1s[idx] = h0in[256 + idx];
        h2s[idx] = h0in[512 + idx];
    }
    if (tid < 16) {
        int rg = ((tid >> 2) << 8) + j0 + (tid & 3);
        biasA[tid] = bih[rg] + bhh[rg];
        biasB[tid] = bih[1024 + rg] + bhh[1024 + rg];
        biasC[tid] = bih[2048 + rg] + bhh[2048 + rg];
    }
    if (tid < U)  b1r[tid] = b1[j0 + tid];
    if (tid < 33) b2s[tid] = b2[tid];

    float cA = 0.f, cB = 0.f, cC = 0.f;     // cell states in warp0 lanes 0..3
    if (tid < U) {
        cA = c0in[j0 + tid];
        cB = c0in[256 + j0 + tid];
        cC = c0in[512 + j0 + tid];
    }
    int ch = 0;
    __syncthreads();

    // ---- Initial recurrent partials from h(t=0): rows 2w, 2w+1 per warp ----
    {
        int r0 = 2 * wid, r1 = 2 * wid + 1;
        float a0 = dot256(l0w + r0 * 512 + 256, h0s, lane);
        float a1 = dot256(l0w + r1 * 512 + 256, h0s, lane);
        float b0 = dot256(wh1 + r0 * 256, h1s, lane);
        float b1v = dot256(wh1 + r1 * 256, h1s, lane);
        float c0 = dot256(wh2 + r0 * 256, h2s, lane);
        float c1 = dot256(wh2 + r1 * 256, h2s, lane);
        wreduce2(a0, a1); wreduce2(b0, b1v); wreduce2(c0, c1);
        if (lane == 0) {
            pA[r0] = a0 + biasA[r0]; pA[r1] = a1 + biasA[r1];
            pB[r0] = b0 + biasB[r0]; pB[r1] = b1v + biasB[r1];
            pC[r0] = c0 + biasC[r0]; pC[r1] = c1 + biasC[r1];
        }
    }
    __syncthreads();

    for (int t = 0; t < T_STEPS; t++) {
        const unsigned seq = (unsigned)(t + 1);

        // ===== Phase A (lite): embed dot + precomputed recurrent partial =====
        {
            int r0 = 2 * wid, r1 = 2 * wid + 1;
            const float* e = embs + ch * 256;
            float s0 = dot256(l0w + r0 * 512, e, lane);
            float s1 = dot256(l0w + r1 * 512, e, lane);
            wreduce2(s0, s1);
            if (lane == 0) {
                float ga = s0 + pA[r0], gb = s1 + pA[r1];
                gT[r0] = ((r0 >> 2) == 2) ? ftanh(ga) : fsig(ga);
                gT[r1] = ((r1 >> 2) == 2) ? ftanh(gb) : fsig(gb);
            }
        }
        __syncthreads();
        if (wid == 0) {
            float h = 0.f;
            if (lane < U) {
                cA = gT[4 + lane] * cA + gT[lane] * gT[8 + lane];
                h  = gT[12 + lane] * ftanh(cA);
            }
            float h1v = __shfl_sync(0xffffffffu, h, 1);
            float h2v = __shfl_sync(0xffffffffu, h, 2);
            float h3v = __shfl_sync(0xffffffffu, h, 3);
            if (lane == 0) {
                stv4(&g_comm[0][k * CSTRIDE],     h,   h1v, seq);
                stv4(&g_comm[0][k * CSTRIDE + 1], h2v, h3v, seq);
            }
        }

        // ===== Phase B: wait all h0, layer1 gates =====
        gather(0, h0s, seq, wid, lane);
        {
            int r0 = 2 * wid, r1 = 2 * wid + 1;
            float s0 = dot256(wi1 + r0 * 256, h0s, lane);
            float s1 = dot256(wi1 + r1 * 256, h0s, lane);
            wreduce2(s0, s1);
            if (lane == 0) {
                float ga = s0 + pB[r0], gb = s1 + pB[r1];
                gT[r0] = ((r0 >> 2) == 2) ? ftanh(ga) : fsig(ga);
                gT[r1] = ((r1 >> 2) == 2) ? ftanh(gb) : fsig(gb);
            }
        }
        __syncthreads();
        if (wid == 0) {
            float h = 0.f;
            if (lane < U) {
                cB = gT[4 + lane] * cB + gT[lane] * gT[8 + lane];
                h  = gT[12 + lane] * ftanh(cB);
            }
            float h1v = __shfl_sync(0xffffffffu, h, 1);
            float h2v = __shfl_sync(0xffffffffu, h, 2);
            float h3v = __shfl_sync(0xffffffffu, h, 3);
            if (lane == 0) {
                stv4(&g_comm[1][k * CSTRIDE],     h,   h1v, seq);
                stv4(&g_comm[1][k * CSTRIDE + 1], h2v, h3v, seq);
            }
        }

        // ===== Phase C: wait all h1, layer2 gates =====
        gather(1, h1s, seq, wid, lane);
        {
            int r0 = 2 * wid, r1 = 2 * wid + 1;
            float s0 = dot256(wi2 + r0 * 256, h1s, lane);
            float s1 = dot256(wi2 + r1 * 256, h1s, lane);
            wreduce2(s0, s1);
            if (lane == 0) {
                float ga = s0 + pC[r0], gb = s1 + pC[r1];
                gT[r0] = ((r0 >> 2) == 2) ? ftanh(ga) : fsig(ga);
                gT[r1] = ((r1 >> 2) == 2) ? ftanh(gb) : fsig(gb);
            }
        }
        __syncthreads();
        if (wid == 0) {
            float h = 0.f;
            if (lane < U) {
                cC = gT[4 + lane] * cC + gT[lane] * gT[8 + lane];
                h  = gT[12 + lane] * ftanh(cC);
            }
            float h1v = __shfl_sync(0xffffffffu, h, 1);
            float h2v = __shfl_sync(0xffffffffu, h, 2);
            float h3v = __shfl_sync(0xffffffffu, h, 3);
            if (lane == 0) {
                stv4(&g_comm[2][k * CSTRIDE],     h,   h1v, seq);
                stv4(&g_comm[2][k * CSTRIDE + 1], h2v, h3v, seq);
            }
        }

        // ===== Phase D: wait all h2; warp0 publishes 4 r rows =====
        gather(2, h2s, seq, wid, lane);
        if (wid == 0) {
            float s0 = dot256(w1r,       h2s, lane);
            float s1 = dot256(w1r + 256, h2s, lane);
            float s2 = dot256(w1r + 512, h2s, lane);
            float s3 = dot256(w1r + 768, h2s, lane);
            wreduce4(s0, s1, s2, s3);
            if (lane == 0) {
                float r0 = fmaxf(s0 + b1r[0], 0.f);
                float r1 = fmaxf(s1 + b1r[1], 0.f);
                float r2 = fmaxf(s2 + b1r[2], 0.f);
                float r3 = fmaxf(s3 + b1r[3], 0.f);
                stv4(&g_comm[3][k * CSTRIDE],     r0, r1, seq);
                stv4(&g_comm[3][k * CSTRIDE + 1], r2, r3, seq);
            }
        }
        // Overlap (off critical path): next step's recurrent partials
        {
            int r0 = 2 * wid, r1 = 2 * wid + 1;
            float a0 = dot256(l0w + r0 * 512 + 256, h0s, lane);
            float a1 = dot256(l0w + r1 * 512 + 256, h0s, lane);
            float b0 = dot256(wh1 + r0 * 256, h1s, lane);
            float b1v = dot256(wh1 + r1 * 256, h1s, lane);
            float c0 = dot256(wh2 + r0 * 256, h2s, lane);
            float c1 = dot256(wh2 + r1 * 256, h2s, lane);
            wreduce2(a0, a1); wreduce2(b0, b1v); wreduce2(c0, c1);
            if (lane == 0) {
                pA[r0] = a0 + biasA[r0]; pA[r1] = a1 + biasA[r1];
                pB[r0] = b0 + biasB[r0]; pB[r1] = b1v + biasB[r1];
                pC[r0] = c0 + biasC[r0]; pC[r1] = c1 + biasC[r1];
            }
        }

        // ===== Phase E: wait all r, redundant classifier + argmax + output =====
        gather(3, rs, seq, wid, lane);
        {
            float s0 = dot256(w2s + wid * 256, rs, lane);
            float s1 = dot256(w2s + (wid + 8) * 256, rs, lane);
            float s2 = dot256(w2s + (wid + 16) * 256, rs, lane);
            float s3 = dot256(w2s + (wid + 24) * 256, rs, lane);
            wreduce4(s0, s1, s2, s3);
            if (lane == 0) {
                pred[wid]      = s0 + b2s[wid];
                pred[wid + 8]  = s1 + b2s[wid + 8];
                pred[wid + 16] = s2 + b2s[wid + 16];
                pred[wid + 24] = s3 + b2s[wid + 24];
            }
            if (wid == 0) {
                float s4 = wreduce(dot256(w2s + 32 * 256, rs, lane));
                if (lane == 0) pred[32] = s4 + b2s[32];
            }
        }
        __syncthreads();
        {
            float best = pred[0];
            int bi = 0;
#pragma unroll
            for (int v = 1; v < 33; v++) {
                float p = pred[v];
                if (p > best) { best = p; bi = v; }
            }
            ch = bi;   // bit-identical in every CTA -> uniform feedback
        }
        // write this CTA's 16 identical batch rows: out[b, t, 0:33]
        for (int idx = tid; idx < 16 * 33; idx += TPB) {
            int bl = idx / 33, v = idx - bl * 33;
            out[((size_t)(k * 16 + bl) * T_STEPS + t) * 33 + v] = pred[v];
        }
    }
}

extern "C" void kernel_launch(void* const* d_in, const int* in_sizes, int n_in,
                              void* d_out, int out_size) {
    // metadata order: labels, embed, Wih0, Wih_rest, Whh, bih, bhh,
    //                 W1, b1, W2, b2, h0, c0
    const float* embed = (const float*)d_in[1];
    const float* Wih0  = (const float*)d_in[2];
    const float* Wihr  = (const float*)d_in[3];
    const float* Whh   = (const float*)d_in[4];
    const float* bih   = (const float*)d_in[5];
    const float* bhh   = (const float*)d_in[6];
    const float* W1    = (const float*)d_in[7];
    const float* b1    = (const float*)d_in[8];
    const float* W2    = (const float*)d_in[9];
    const float* b2    = (const float*)d_in[10];
    const float* h0    = (const float*)d_in[11];
    const float* c0    = (const float*)d_in[12];
    float* out = (float*)d_out;

    size_t smem = (size_t)SMEM_FLOATS * sizeof(float);
    cudaFuncSetAttribute(speller_kernel,
                         cudaFuncAttributeMaxDynamicSharedMemorySize,
                         (int)smem);
    speller_kernel<<<G, TPB, smem>>>(embed, Wih0, Wihr, Whh, bih, bhh,
                                     W1, b1, W2, b2, h0, c0, out);
}

// round 10
// speedup vs baseline: 1.1834x; 1.0179x over previous
#include <cuda_runtime.h>

#define G 128
#define TPB 256
#define T_STEPS 220
#define CS 16    // float4 stride per CTA slot group (256B -> L2 slice spread)

// Seqlock exchange: per phase, CTA k owns two half-slots (same 32B sector):
//   [k*CS+0] = {v0,v0,seq,seq}   (published by warp0)
//   [k*CS+1] = {v1,v1,seq,seq}   (published by warp1)
// Data+flag arrive in one 16B volatile load.
__device__ float4 g_comm[4][G * CS];

__device__ __forceinline__ void ldv4(const float4* p, float& a,
                                     unsigned& s0, unsigned& s1) {
    unsigned x, y;
    asm volatile("ld.volatile.global.v4.b32 {%0,%1,%2,%3}, [%4];"
                 : "=r"(x), "=r"(y), "=r"(s0), "=r"(s1) : "l"(p));
    a = __uint_as_float(x);
}
__device__ __forceinline__ void stv4(float4* p, float v, unsigned s) {
    asm volatile("st.volatile.global.v4.b32 [%0], {%1,%2,%3,%4};"
                 :: "l"(p), "r"(__float_as_uint(v)), "r"(__float_as_uint(v)),
                    "r"(s), "r"(s));
}
__device__ __forceinline__ float wreduce(float v) {
#pragma unroll
    for (int m = 16; m >= 1; m >>= 1) v += __shfl_xor_sync(0xffffffffu, v, m);
    return v;
}
__device__ __forceinline__ void wreduce2(float& a, float& b) {
#pragma unroll
    for (int m = 16; m >= 1; m >>= 1) {
        a += __shfl_xor_sync(0xffffffffu, a, m);
        b += __shfl_xor_sync(0xffffffffu, b, m);
    }
}
__device__ __forceinline__ void wreduce4(float& a, float& b, float& c, float& d) {
#pragma unroll
    for (int m = 16; m >= 1; m >>= 1) {
        a += __shfl_xor_sync(0xffffffffu, a, m);
        b += __shfl_xor_sync(0xffffffffu, b, m);
        c += __shfl_xor_sync(0xffffffffu, c, m);
        d += __shfl_xor_sync(0xffffffffu, d, m);
    }
}
__device__ __forceinline__ float fsig(float x) {
    return __fdividef(1.0f, 1.0f + __expf(-x));
}
__device__ __forceinline__ float ftanh(float x) {
    return 1.0f - __fdividef(2.0f, __expf(2.0f * x) + 1.0f);
}
__device__ __forceinline__ float dot256(const float* w, const float* x, int lane) {
    const float4* w4 = (const float4*)w;
    const float4* x4 = (const float4*)x;
    float s = 0.f;
#pragma unroll
    for (int i = 0; i < 2; i++) {
        float4 a = w4[i * 32 + lane], b = x4[i * 32 + lane];
        s += a.x * b.x + a.y * b.y + a.z * b.z + a.w * b.w;
    }
    return s;
}
// Warps 0-3: lane s polls both half-slots of CTA s (non-predicated, R6-style).
__device__ __forceinline__ void gather(int phase, float* dst, unsigned seq,
                                       int wid, int lane) {
    if (wid < 4) {
        int s = wid * 32 + lane;
        const float4* p0 = &g_comm[phase][s * CS];
        float a0, a1;
        unsigned x0, y0, x1, y1;
        for (;;) {
            ldv4(p0,     a0, x0, y0);
            ldv4(p0 + 1, a1, x1, y1);
            if (__all_sync(0xffffffffu,
                           (x0 == seq) & (y0 == seq) & (x1 == seq) & (y1 == seq)))
                break;
        }
        dst[2 * s]     = a0;
        dst[2 * s + 1] = a1;
    }
    __syncthreads();
}

// SMEM layout (floats)
#define OFF_L0W   0                 // 8 x 512  layer0 [Wih x-part | Whh]
#define OFF_WH1   4096              // 8 x 256
#define OFF_WH2   6144
#define OFF_WI1   8192
#define OFF_WI2   10240
#define OFF_W1R   12288             // 2 x 256
#define OFF_W2S   12800             // 33 x 256
#define OFF_TBL   21248             // 33 x 8 embed-projection table
#define OFF_H0S   21520             // 256
#define OFF_H1S   21776
#define OFF_H2S   22032
#define OFF_RS    22288
#define OFF_PA    22544             // 8
#define OFF_PB    22552
#define OFF_PC    22560
#define OFF_PRED  22568             // 33 (+pad)
#define OFF_BA    22604             // 8
#define OFF_BB    22612
#define OFF_BC    22620
#define OFF_B1R   22628             // 2
#define OFF_B2S   22630             // 33
#define SMEM_FLOATS 22664

__global__ void __launch_bounds__(TPB, 1)
speller_kernel(const float* __restrict__ embed_g,
               const float* __restrict__ Wih0,
               const float* __restrict__ Wihr,
               const float* __restrict__ Whh,
               const float* __restrict__ bih,
               const float* __restrict__ bhh,
               const float* __restrict__ W1,
               const float* __restrict__ b1,
               const float* __restrict__ W2,
               const float* __restrict__ b2,
               const float* __restrict__ h0in,
               const float* __restrict__ c0in,
               float* __restrict__ out)
{
    extern __shared__ float sm[];
    float* l0w  = sm + OFF_L0W;
    float* wh1  = sm + OFF_WH1;
    float* wh2  = sm + OFF_WH2;
    float* wi1  = sm + OFF_WI1;
    float* wi2  = sm + OFF_WI2;
    float* w1r  = sm + OFF_W1R;
    float* w2s  = sm + OFF_W2S;
    float* tbl  = sm + OFF_TBL;
    float* h0s  = sm + OFF_H0S;
    float* h1s  = sm + OFF_H1S;
    float* h2s  = sm + OFF_H2S;
    float* rs   = sm + OFF_RS;
    float* pA   = sm + OFF_PA;
    float* pB   = sm + OFF_PB;
    float* pC   = sm + OFF_PC;
    float* pred = sm + OFF_PRED;
    float* biasA = sm + OFF_BA;
    float* biasB = sm + OFF_BB;
    float* biasC = sm + OFF_BC;
    float* b1r  = sm + OFF_B1R;
    float* b2s  = sm + OFF_B2S;

    const int tid  = threadIdx.x;
    const int wid  = tid >> 5;
    const int lane = tid & 31;
    const int k    = blockIdx.x;
    const int j0   = 2 * k;          // this CTA's first hidden unit

    // ---- One-time weight staging (ctx columns all-zero: dropped) ----
    // local gate row r = gate*2 + u  -> global row rg = gate*256 + j0 + u
    for (int idx = tid; idx < 8 * 512; idx += TPB) {
        int r = idx >> 9, c = idx & 511;
        int rg = ((r >> 1) << 8) + j0 + (r & 1);
        l0w[idx] = (c < 256) ? Wih0[rg * 384 + c] : Whh[rg * 256 + (c - 256)];
    }
    for (int idx = tid; idx < 8 * 256; idx += TPB) {
        int r = idx >> 8, c = idx & 255;
        int rg = ((r >> 1) << 8) + j0 + (r & 1);
        wh1[idx] = Whh[(1024 + rg) * 256 + c];
        wh2[idx] = Whh[(2048 + rg) * 256 + c];
        wi1[idx] = Wihr[rg * 256 + c];
        wi2[idx] = Wihr[(1024 + rg) * 256 + c];
    }
    for (int idx = tid; idx < 512; idx += TPB) {
        int u = idx >> 8, c = idx & 255;
        w1r[idx] = W1[(j0 + u) * 384 + c];
    }
    for (int idx = tid; idx < 33 * 256; idx += TPB) w2s[idx] = W2[idx];
    for (int idx = tid; idx < 256; idx += TPB) {
        h0s[idx] = h0in[idx];
        h1s[idx] = h0in[256 + idx];
        h2s[idx] = h0in[512 + idx];
    }
    if (tid < 8) {
        int rg = ((tid >> 1) << 8) + j0 + (tid & 1);
        biasA[tid] = bih[rg] + bhh[rg];
        biasB[tid] = bih[1024 + rg] + bhh[1024 + rg];
        biasC[tid] = bih[2048 + rg] + bhh[2048 + rg];
    }
    if (tid < 2)  b1r[tid] = b1[j0 + tid];
    if (tid < 33) b2s[tid] = b2[tid];

    float cA = 0.f, cB = 0.f, cC = 0.f;   // cell states: warp u (0/1), lane 0
    if (wid < 2 && lane == 0) {
        cA = c0in[j0 + wid];
        cB = c0in[256 + j0 + wid];
        cC = c0in[512 + j0 + wid];
    }
    int ch = 0;
    __syncthreads();

    // ---- Embed-projection table: tbl[v*8+r] = Wih0_row_r . emb[v] ----
    // warp w owns row r=w; 33 dots from global embed (L2-warm after first).
    {
        for (int v = 0; v < 33; v++) {
            float s = wreduce(dot256(l0w + wid * 512, embed_g + v * 256, lane));
            if (lane == 0) tbl[v * 8 + wid] = s;
        }
    }
    // ---- Initial recurrent partials from h(0) (warps 4-7, rows 2w',2w'+1) ----
    if (wid >= 4) {
        int r0 = 2 * (wid - 4), r1 = r0 + 1;
        float a0 = dot256(l0w + r0 * 512 + 256, h0s, lane);
        float a1 = dot256(l0w + r1 * 512 + 256, h0s, lane);
        float e0 = dot256(wh1 + r0 * 256, h1s, lane);
        float e1 = dot256(wh1 + r1 * 256, h1s, lane);
        float f0 = dot256(wh2 + r0 * 256, h2s, lane);
        float f1 = dot256(wh2 + r1 * 256, h2s, lane);
        wreduce2(a0, a1); wreduce2(e0, e1); wreduce2(f0, f1);
        if (lane == 0) {
            pA[r0] = a0 + biasA[r0]; pA[r1] = a1 + biasA[r1];
            pB[r0] = e0 + biasB[r0]; pB[r1] = e1 + biasB[r1];
            pC[r0] = f0 + biasC[r0]; pC[r1] = f1 + biasC[r1];
        }
    }
    __syncthreads();

    for (int t = 0; t < T_STEPS; t++) {
        const unsigned seq = (unsigned)(t + 1);

        // ===== Phase A: warps 0,1 — table lookup + cell, no barriers =====
        if (wid < 2) {
            float v = 0.f;
            if (lane < 4) {
                int r = 2 * lane + wid;          // gate=lane, unit=wid
                float g = tbl[ch * 8 + r] + pA[r];
                v = (lane == 2) ? ftanh(g) : fsig(g);
            }
            float ig = __shfl_sync(0xffffffffu, v, 0);
            float fg = __shfl_sync(0xffffffffu, v, 1);
            float gg = __shfl_sync(0xffffffffu, v, 2);
            float og = __shfl_sync(0xffffffffu, v, 3);
            if (lane == 0) {
                cA = fg * cA + ig * gg;
                float h = og * ftanh(cA);
                stv4(&g_comm[0][k * CS + wid], h, seq);
            }
        }

        // ===== Phase B: wait all h0; warps 0,1 own their unit's 4 gates =====
        gather(0, h0s, seq, wid, lane);
        if (wid < 2) {
            float si = dot256(wi1 + (0 + wid) * 256, h0s, lane);
            float sf = dot256(wi1 + (2 + wid) * 256, h0s, lane);
            float sg = dot256(wi1 + (4 + wid) * 256, h0s, lane);
            float so = dot256(wi1 + (6 + wid) * 256, h0s, lane);
            wreduce4(si, sf, sg, so);
            if (lane == 0) {
                float gi = fsig(si + pB[0 + wid]);
                float gf = fsig(sf + pB[2 + wid]);
                float gg = ftanh(sg + pB[4 + wid]);
                float go = fsig(so + pB[6 + wid]);
                cB = gf * cB + gi * gg;
                float h = go * ftanh(cB);
                stv4(&g_comm[1][k * CS + wid], h, seq);
            }
        }

        // ===== Phase C: wait all h1 =====
        gather(1, h1s, seq, wid, lane);
        if (wid < 2) {
            float si = dot256(wi2 + (0 + wid) * 256, h1s, lane);
            float sf = dot256(wi2 + (2 + wid) * 256, h1s, lane);
            float sg = dot256(wi2 + (4 + wid) * 256, h1s, lane);
            float so = dot256(wi2 + (6 + wid) * 256, h1s, lane);
            wreduce4(si, sf, sg, so);
            if (lane == 0) {
                float gi = fsig(si + pC[0 + wid]);
                float gf = fsig(sf + pC[2 + wid]);
                float gg = ftanh(sg + pC[4 + wid]);
                float go = fsig(so + pC[6 + wid]);
                cC = gf * cC + gi * gg;
                float h = go * ftanh(cC);
                stv4(&g_comm[2][k * CS + wid], h, seq);
            }
        }

        // ===== Phase D: wait all h2; warps 0,1 publish one r row each =====
        gather(2, h2s, seq, wid, lane);
        if (wid < 2) {
            float s = wreduce(dot256(w1r + wid * 256, h2s, lane));
            if (lane == 0) {
                float r = fmaxf(s + b1r[wid], 0.f);
                stv4(&g_comm[3][k * CS + wid], r, seq);
            }
        }
        // Next-step recurrent partials on warps 4-7 (off the E-poll path)
        if (wid >= 4) {
            int r0 = 2 * (wid - 4), r1 = r0 + 1;
            float a0 = dot256(l0w + r0 * 512 + 256, h0s, lane);
            float a1 = dot256(l0w + r1 * 512 + 256, h0s, lane);
            float e0 = dot256(wh1 + r0 * 256, h1s, lane);
            float e1 = dot256(wh1 + r1 * 256, h1s, lane);
            float f0 = dot256(wh2 + r0 * 256, h2s, lane);
            float f1 = dot256(wh2 + r1 * 256, h2s, lane);
            wreduce2(a0, a1); wreduce2(e0, e1); wreduce2(f0, f1);
            if (lane == 0) {
                pA[r0] = a0 + biasA[r0]; pA[r1] = a1 + biasA[r1];
                pB[r0] = e0 + biasB[r0]; pB[r1] = e1 + biasB[r1];
                pC[r0] = f0 + biasC[r0]; pC[r1] = f1 + biasC[r1];
            }
        }

        // ===== Phase E: wait all r; pred on warps 0-3; argmax everywhere =====
        gather(3, rs, seq, wid, lane);
        if (wid < 4) {
            float s0 = dot256(w2s + wid * 256, rs, lane);
            float s1 = dot256(w2s + (wid + 4) * 256, rs, lane);
            float s2 = dot256(w2s + (wid + 8) * 256, rs, lane);
            float s3 = dot256(w2s + (wid + 12) * 256, rs, lane);
            wreduce4(s0, s1, s2, s3);
            float s4 = dot256(w2s + (wid + 16) * 256, rs, lane);
            float s5 = dot256(w2s + (wid + 20) * 256, rs, lane);
            float s6 = dot256(w2s + (wid + 24) * 256, rs, lane);
            float s7 = dot256(w2s + (wid + 28) * 256, rs, lane);
            wreduce4(s4, s5, s6, s7);
            if (lane == 0) {
                pred[wid]      = s0 + b2s[wid];
                pred[wid + 4]  = s1 + b2s[wid + 4];
                pred[wid + 8]  = s2 + b2s[wid + 8];
                pred[wid + 12] = s3 + b2s[wid + 12];
                pred[wid + 16] = s4 + b2s[wid + 16];
                pred[wid + 20] = s5 + b2s[wid + 20];
                pred[wid + 24] = s6 + b2s[wid + 24];
                pred[wid + 28] = s7 + b2s[wid + 28];
            }
            if (wid == 0) {
                float s8 = wreduce(dot256(w2s + 32 * 256, rs, lane));
                if (lane == 0) pred[32] = s8 + b2s[32];
            }
        }
        __syncthreads();
        {
            float best = pred[0];
            int bi = 0;
#pragma unroll
            for (int v = 1; v < 33; v++) {
                float p = pred[v];
                if (p > best) { best = p; bi = v; }
            }
            ch = bi;   // bit-identical across CTAs -> uniform feedback
        }
        // Output: warps 4-7 write this CTA's 8 identical batch rows.
        if (wid >= 4) {
            int idx = (wid - 4) * 32 + lane;   // 0..127
#pragma unroll
            for (int rep = 0; rep < 2; rep++) {
                int e = idx + rep * 128;       // 0..255
                int bl = e / 33, v = e - bl * 33;
                out[((size_t)(j0 * 4 + bl) * T_STEPS + t) * 33 + v] = pred[v];
            }
            if (idx < 8) {   // elements 256..263
                int e = idx + 256;
                int bl = e / 33, v = e - bl * 33;
                out[((size_t)(j0 * 4 + bl) * T_STEPS + t) * 33 + v] = pred[v];
            }
        }
        // pred/rs/h*s reuse is fenced by the gathers' __syncthreads next step.
    }
}

extern "C" void kernel_launch(void* const* d_in, const int* in_sizes, int n_in,
                              void* d_out, int out_size) {
    // metadata order: labels, embed, Wih0, Wih_rest, Whh, bih, bhh,
    //                 W1, b1, W2, b2, h0, c0
    const float* embed = (const float*)d_in[1];
    const float* Wih0  = (const float*)d_in[2];
    const float* Wihr  = (const float*)d_in[3];
    const float* Whh   = (const float*)d_in[4];
    const float* bih   = (const float*)d_in[5];
    const float* bhh   = (const float*)d_in[6];
    const float* W1    = (const float*)d_in[7];
    const float* b1    = (const float*)d_in[8];
    const float* W2    = (const float*)d_in[9];
    const float* b2    = (const float*)d_in[10];
    const float* h0    = (const float*)d_in[11];
    const float* c0    = (const float*)d_in[12];
    float* out = (float*)d_out;

    size_t smem = (size_t)SMEM_FLOATS * sizeof(float);
    cudaFuncSetAttribute(speller_kernel,
                         cudaFuncAttributeMaxDynamicSharedMemorySize,
                         (int)smem);
    speller_kernel<<<G, TPB, smem>>>(embed, Wih0, Wihr, Whh, bih, bhh,
                                     W1, b1, W2, b2, h0, c0, out);
}

// round 11
// speedup vs baseline: 1.3730x; 1.1603x over previous
#include <cuda_runtime.h>

#define G 128
#define TPB 256
#define T_STEPS 220
#define CSTRIDE 16   // float4s per slot: 256B -> spreads L2 slice hash bits

// Seqlock exchange buffers: {val0, val1, seq, seq} per CTA, 256B-strided
// (round-6 proven layout; data + flag in one 16B volatile load).
__device__ float4 g_h0buf[G * CSTRIDE];
__device__ float4 g_h1buf[G * CSTRIDE];
__device__ float4 g_h2buf[G * CSTRIDE];
__device__ float4 g_rbuf [G * CSTRIDE];

__device__ __forceinline__ void ldv4(const float4* p, float& a, float& b,
                                     unsigned& s0, unsigned& s1) {
    unsigned x, y;
    asm volatile("ld.volatile.global.v4.b32 {%0,%1,%2,%3}, [%4];"
                 : "=r"(x), "=r"(y), "=r"(s0), "=r"(s1) : "l"(p));
    a = __uint_as_float(x);
    b = __uint_as_float(y);
}
__device__ __forceinline__ void stv4(float4* p, float a, float b, unsigned s) {
    asm volatile("st.volatile.global.v4.b32 [%0], {%1,%2,%3,%4};"
                 :: "l"(p), "r"(__float_as_uint(a)), "r"(__float_as_uint(b)),
                    "r"(s), "r"(s));
}
__device__ __forceinline__ float wreduce(float v) {
#pragma unroll
    for (int m = 16; m >= 1; m >>= 1) v += __shfl_xor_sync(0xffffffffu, v, m);
    return v;
}
__device__ __forceinline__ void wreduce2(float& a, float& b) {
#pragma unroll
    for (int m = 16; m >= 1; m >>= 1) {
        a += __shfl_xor_sync(0xffffffffu, a, m);
        b += __shfl_xor_sync(0xffffffffu, b, m);
    }
}
__device__ __forceinline__ void wreduce4(float& a, float& b, float& c, float& d) {
#pragma unroll
    for (int m = 16; m >= 1; m >>= 1) {
        a += __shfl_xor_sync(0xffffffffu, a, m);
        b += __shfl_xor_sync(0xffffffffu, b, m);
        c += __shfl_xor_sync(0xffffffffu, c, m);
        d += __shfl_xor_sync(0xffffffffu, d, m);
    }
}
__device__ __forceinline__ void wreduce5(float& a, float& b, float& c,
                                         float& d, float& e) {
#pragma unroll
    for (int m = 16; m >= 1; m >>= 1) {
        a += __shfl_xor_sync(0xffffffffu, a, m);
        b += __shfl_xor_sync(0xffffffffu, b, m);
        c += __shfl_xor_sync(0xffffffffu, c, m);
        d += __shfl_xor_sync(0xffffffffu, d, m);
        e += __shfl_xor_sync(0xffffffffu, e, m);
    }
}
// Fast activations (~1e-6 rel err; argmax-safe vs observed 3e-7 pipeline err)
__device__ __forceinline__ float fsig(float x) {
    return __fdividef(1.0f, 1.0f + __expf(-x));
}
__device__ __forceinline__ float ftanh(float x) {
    return 1.0f - __fdividef(2.0f, __expf(2.0f * x) + 1.0f);
}
__device__ __forceinline__ float dot256(const float* w, const float* x, int lane) {
    const float4* w4 = (const float4*)w;
    const float4* x4 = (const float4*)x;
    float s = 0.f;
#pragma unroll
    for (int i = 0; i < 2; i++) {
        float4 a = w4[i * 32 + lane], b = x4[i * 32 + lane];
        s += a.x * b.x + a.y * b.y + a.z * b.z + a.w * b.w;
    }
    return s;
}
// Round-6 gather verbatim: warps 0-3 poll 128 strided slots, one load/lane.
__device__ __forceinline__ void gather(const float4* buf, float* dst,
                                       unsigned seq, int wid, int lane) {
    if (wid < 4) {
        int s = wid * 32 + lane;
        const float4* p = buf + (size_t)s * CSTRIDE;
        float a, b;
        unsigned s0, s1;
        for (;;) {
            ldv4(p, a, b, s0, s1);
            if (__all_sync(0xffffffffu, (s0 == seq) & (s1 == seq))) break;
        }
        dst[2 * s]     = a;
        dst[2 * s + 1] = b;
    }
    __syncthreads();
}

// SMEM layout (floats)
#define OFF_L0W   0       // 8 x 512  layer0 [Wih(:,0:256) | Whh]
#define OFF_WH1   4096    // 8 x 256
#define OFF_WH2   6144
#define OFF_WI1   8192
#define OFF_WI2   10240
#define OFF_W1R   12288   // 2 x 256
#define OFF_W2S   12800   // 33 x 256
#define OFF_TBL   21248   // 33 x 8 embed-projection table
#define OFF_H0S   21512   // 256 (16B aligned: /4 divisible)
#define OFF_H1S   21768
#define OFF_H2S   22024
#define OFF_RS    22280
#define OFF_GT    22536   // 8
#define OFF_PA    22544   // 8
#define OFF_PB    22552
#define OFF_PC    22560
#define OFF_PRED  22568   // 33 (+pad)
#define OFF_BA    22604   // 8
#define OFF_BB    22612
#define OFF_BC    22620
#define OFF_B1R   22628   // 2
#define OFF_B2S   22630   // 33
#define SMEM_FLOATS 22664

__global__ void __launch_bounds__(TPB, 1)
speller_kernel(const float* __restrict__ embed_g,
               const float* __restrict__ Wih0,
               const float* __restrict__ Wihr,
               const float* __restrict__ Whh,
               const float* __restrict__ bih,
               const float* __restrict__ bhh,
               const float* __restrict__ W1,
               const float* __restrict__ b1,
               const float* __restrict__ W2,
               const float* __restrict__ b2,
               const float* __restrict__ h0in,
               const float* __restrict__ c0in,
               float* __restrict__ out)
{
    extern __shared__ float sm[];
    float* l0w  = sm + OFF_L0W;
    float* wh1  = sm + OFF_WH1;
    float* wh2  = sm + OFF_WH2;
    float* wi1  = sm + OFF_WI1;
    float* wi2  = sm + OFF_WI2;
    float* w1r  = sm + OFF_W1R;
    float* w2s  = sm + OFF_W2S;
    float* tbl  = sm + OFF_TBL;
    float* h0s  = sm + OFF_H0S;
    float* h1s  = sm + OFF_H1S;
    float* h2s  = sm + OFF_H2S;
    float* rs   = sm + OFF_RS;
    float* gT   = sm + OFF_GT;
    float* pA   = sm + OFF_PA;
    float* pB   = sm + OFF_PB;
    float* pC   = sm + OFF_PC;
    float* pred = sm + OFF_PRED;
    float* biasA = sm + OFF_BA;
    float* biasB = sm + OFF_BB;
    float* biasC = sm + OFF_BC;
    float* b1r  = sm + OFF_B1R;
    float* b2s  = sm + OFF_B2S;

    const int tid  = threadIdx.x;
    const int wid  = tid >> 5;
    const int lane = tid & 31;
    const int k    = blockIdx.x;
    const int j0   = 2 * k;          // this CTA's hidden-unit pair

    // ---- One-time weight staging (ctx columns are all-zero: dropped) ----
    // local gate row r = gate*2 + u  (i:0,1  f:2,3  g:4,5  o:6,7)
    for (int idx = tid; idx < 8 * 512; idx += TPB) {
        int r = idx >> 9, c = idx & 511;
        int rg = ((r >> 1) << 8) + j0 + (r & 1);
        l0w[idx] = (c < 256) ? Wih0[rg * 384 + c] : Whh[rg * 256 + (c - 256)];
    }
    for (int idx = tid; idx < 8 * 256; idx += TPB) {
        int r = idx >> 8, c = idx & 255;
        int rg = ((r >> 1) << 8) + j0 + (r & 1);
        wh1[idx] = Whh[(1024 + rg) * 256 + c];
        wh2[idx] = Whh[(2048 + rg) * 256 + c];
        wi1[idx] = Wihr[rg * 256 + c];
        wi2[idx] = Wihr[(1024 + rg) * 256 + c];
    }
    for (int idx = tid; idx < 512; idx += TPB) {
        int u = idx >> 8, c = idx & 255;
        w1r[idx] = W1[(j0 + u) * 384 + c];
    }
    for (int idx = tid; idx < 33 * 256; idx += TPB) w2s[idx] = W2[idx];
    for (int idx = tid; idx < 256; idx += TPB) {
        h0s[idx] = h0in[idx];
        h1s[idx] = h0in[256 + idx];
        h2s[idx] = h0in[512 + idx];
    }
    if (tid < 8) {
        int rg = ((tid >> 1) << 8) + j0 + (tid & 1);
        biasA[tid] = bih[rg] + bhh[rg];
        biasB[tid] = bih[1024 + rg] + bhh[1024 + rg];
        biasC[tid] = bih[2048 + rg] + bhh[2048 + rg];
    }
    if (tid < 2)  b1r[tid] = b1[j0 + tid];
    if (tid < 33) b2s[tid] = b2[tid];

    float cA = 0.f, cB = 0.f, cC = 0.f;     // cell states in warp0 lanes 0,1
    if (tid < 2) {
        cA = c0in[j0 + tid];
        cB = c0in[256 + j0 + tid];
        cC = c0in[512 + j0 + tid];
    }
    int ch = 0;
    __syncthreads();

    // ---- Embed-projection table: tbl[v*8 + r] = Wih0_row_r . emb[v] ----
    {
        for (int v = 0; v < 33; v++) {
            float s = wreduce(dot256(l0w + wid * 512, embed_g + v * 256, lane));
            if (lane == 0) tbl[v * 8 + wid] = s;
        }
    }
    // ---- Initial recurrent partials from h(t=0) ----
    {
        float s0 = dot256(l0w + wid * 512 + 256, h0s, lane);
        float s1 = dot256(wh1 + wid * 256, h1s, lane);
        float s2 = dot256(wh2 + wid * 256, h2s, lane);
        s0 = wreduce(s0); s1 = wreduce(s1); s2 = wreduce(s2);
        if (lane == 0) {
            pA[wid] = s0 + biasA[wid];
            pB[wid] = s1 + biasB[wid];
            pC[wid] = s2 + biasC[wid];
        }
    }
    __syncthreads();

    // ---- Precomputed output addresses: 264 elems (8 rows x 33) ----
    // thread tid writes element tid; threads 0-7 also write 256+tid.
    float* outp0;
    float* outp1 = 0;
    {
        int bl0 = tid / 33, v0 = tid - bl0 * 33;
        outp0 = out + (size_t)(j0 * 4 + bl0) * T_STEPS * 33 + v0;
        if (tid < 8) {
            int e = 256 + tid;
            int bl1 = e / 33, v1 = e - bl1 * 33;
            outp1 = out + (size_t)(j0 * 4 + bl1) * T_STEPS * 33 + v1;
        }
    }
    const int pv0 = tid - (tid / 33) * 33;
    const int pv1 = (256 + tid) - ((256 + tid) / 33) * 33;

    for (int t = 0; t < T_STEPS; t++) {
        const unsigned seq = (unsigned)(t + 1);

        // ===== Phase A: warp0 only — table lookup + cell, no barriers =====
        if (wid == 0) {
            float v = 0.f;
            if (lane < 8) {
                float g = tbl[ch * 8 + lane] + pA[lane];
                v = (lane == 4 || lane == 5) ? ftanh(g) : fsig(g);
            }
            int u = lane & 1;
            float ig = __shfl_sync(0xffffffffu, v, u);
            float fg = __shfl_sync(0xffffffffu, v, 2 + u);
            float gg = __shfl_sync(0xffffffffu, v, 4 + u);
            float og = __shfl_sync(0xffffffffu, v, 6 + u);
            float h = 0.f;
            if (lane < 2) {
                cA = fg * cA + ig * gg;
                h  = og * ftanh(cA);
            }
            float hb = __shfl_sync(0xffffffffu, h, 1);
            if (lane == 0) stv4(&g_h0buf[k * CSTRIDE], h, hb, seq);
        }

        // ===== Phase B: wait all h0, layer1 gates (round-6 structure) =====
        gather(g_h0buf, h0s, seq, wid, lane);
        {
            float s = wreduce(dot256(wi1 + wid * 256, h0s, lane));
            if (lane == 0) {
                float g = s + pB[wid];
                gT[wid] = (wid == 4 || wid == 5) ? ftanh(g) : fsig(g);
            }
        }
        __syncthreads();
        if (wid == 0) {
            float h = 0.f;
            if (lane < 2) {
                cB = gT[2 + lane] * cB + gT[lane] * gT[4 + lane];
                h  = gT[6 + lane] * ftanh(cB);
            }
            float hb = __shfl_sync(0xffffffffu, h, 1);
            if (lane == 0) stv4(&g_h1buf[k * CSTRIDE], h, hb, seq);
        }

        // ===== Phase C: wait all h1, layer2 gates =====
        gather(g_h1buf, h1s, seq, wid, lane);
        {
            float s = wreduce(dot256(wi2 + wid * 256, h1s, lane));
            if (lane == 0) {
                float g = s + pC[wid];
                gT[wid] = (wid == 4 || wid == 5) ? ftanh(g) : fsig(g);
            }
        }
        __syncthreads();
        if (wid == 0) {
            float h = 0.f;
            if (lane < 2) {
                cC = gT[2 + lane] * cC + gT[lane] * gT[4 + lane];
                h  = gT[6 + lane] * ftanh(cC);
            }
            float hb = __shfl_sync(0xffffffffu, h, 1);
            if (lane == 0) stv4(&g_h2buf[k * CSTRIDE], h, hb, seq);
        }

        // ===== Phase D: wait all h2; warp0 publishes both r rows =====
        gather(g_h2buf, h2s, seq, wid, lane);
        if (wid == 0) {
            float s0 = dot256(w1r, h2s, lane);
            float s1 = dot256(w1r + 256, h2s, lane);
            wreduce2(s0, s1);
            if (lane == 0) {
                float r0 = fmaxf(s0 + b1r[0], 0.f);
                float r1 = fmaxf(s1 + b1r[1], 0.f);
                stv4(&g_rbuf[k * CSTRIDE], r0, r1, seq);
            }
        }
        // Overlap (round-6 placement): next step's recurrent partials
        {
            float s0 = dot256(l0w + wid * 512 + 256, h0s, lane);
            float s1 = dot256(wh1 + wid * 256, h1s, lane);
            float s2 = dot256(wh2 + wid * 256, h2s, lane);
            s0 = wreduce(s0); s1 = wreduce(s1); s2 = wreduce(s2);
            if (lane == 0) {
                pA[wid] = s0 + biasA[wid];
                pB[wid] = s1 + biasB[wid];
                pC[wid] = s2 + biasC[wid];
            }
        }

        // ===== Phase E: wait all r, redundant classifier + argmax + out =====
        gather(g_rbuf, rs, seq, wid, lane);
        {
            float s0 = dot256(w2s + wid * 256, rs, lane);
            float s1 = dot256(w2s + (wid + 8) * 256, rs, lane);
            float s2 = dot256(w2s + (wid + 16) * 256, rs, lane);
            float s3 = dot256(w2s + (wid + 24) * 256, rs, lane);
            if (wid == 0) {
                float s4 = dot256(w2s + 32 * 256, rs, lane);
                wreduce5(s0, s1, s2, s3, s4);   // row 32 interleaved, not serial
                if (lane == 0) pred[32] = s4 + b2s[32];
            } else {
                wreduce4(s0, s1, s2, s3);
            }
            if (lane == 0) {
                pred[wid]      = s0 + b2s[wid];
                pred[wid + 8]  = s1 + b2s[wid + 8];
                pred[wid + 16] = s2 + b2s[wid + 16];
                pred[wid + 24] = s3 + b2s[wid + 24];
            }
        }
        __syncthreads();
        {
            float best = pred[0];
            int bi = 0;
#pragma unroll
            for (int v = 1; v < 33; v++) {
                float p = pred[v];
                if (p > best) { best = p; bi = v; }
            }
            ch = bi;   // bit-identical across CTAs -> uniform feedback
        }
        // Output via hoisted pointers (one STG each; +33 floats per step)
        *outp0 = pred[pv0];
        outp0 += 33;
        if (outp1) {
            *outp1 = pred[pv1];
            outp1 += 33;
        }
    }
}

extern "C" void kernel_launch(void* const* d_in, const int* in_sizes, int n_in,
                              void* d_out, int out_size) {
    // metadata order: labels, embed, Wih0, Wih_rest, Whh, bih, bhh,
    //                 W1, b1, W2, b2, h0, c0
    const float* embed = (const float*)d_in[1];
    const float* Wih0  = (const float*)d_in[2];
    const float* Wihr  = (const float*)d_in[3];
    const float* Whh   = (const float*)d_in[4];
    const float* bih   = (const float*)d_in[5];
    const float* bhh   = (const float*)d_in[6];
    const float* W1    = (const float*)d_in[7];
    const float* b1    = (const float*)d_in[8];
    const float* W2    = (const float*)d_in[9];
    const float* b2    = (const float*)d_in[10];
    const float* h0    = (const float*)d_in[11];
    const float* c0    = (const float*)d_in[12];
    float* out = (float*)d_out;

    size_t smem = (size_t)SMEM_FLOATS * sizeof(float);
    cudaFuncSetAttribute(speller_kernel,
                         cudaFuncAttributeMaxDynamicSharedMemorySize,
                         (int)smem);
    speller_kernel<<<G, TPB, smem>>>(embed, Wih0, Wihr, Whh, bih, bhh,
                                     W1, b1, W2, b2, h0, c0, out);
}